// round 14
// baseline (speedup 1.0000x reference)
#include <cuda_runtime.h>
#include <cuda_bf16.h>
#include <cstdint>

// ---------------- problem dims ----------------
#define LSEQ 2048
#define DMODEL 512
#define DPROJ 2568
#define GN 4          // groups
#define NS 32         // d_state
#define HH 16         // heads
#define PP 64         // head dim
#define NC 16         // chunks
#define CH 128        // chunk len
#define EPSV 1e-5f
#define TAILW 520     // B(256) C(256) dt(4) lam(4)

// ---------------- scratch (device globals; no allocs allowed) ----------------
__device__ float  g_tail [LSEQ*TAILW];        // compact proj tail
__device__ float  g_zsilu[LSEQ*1024];
__device__ float  g_xsilu[LSEQ*1024];
__device__ float  g_Bm   [LSEQ*GN*64];
__device__ float  g_Cm   [LSEQ*GN*64];
__device__ float4 g_scal [LSEQ*GN];           // (dt, lam, decay, 0)
__device__ float  g_sdt  [LSEQ*GN];
__device__ float  g_Dc   [NC*GN];
__device__ float  g_xup  [LSEQ*HH*128];
__device__ float  g_F    [NC*HH*PP*NS];
__device__ float  g_S    [NC*HH*PP*NS];
__device__ float  g_yraw [LSEQ*HH*128];
__device__ float  g_y3   [LSEQ*1024];

// ---------------- bf16-split helpers ----------------
__device__ __forceinline__ void split2(float x, float y, unsigned int& h, unsigned int& l){
    __nv_bfloat162 H = __floats2bfloat162_rn(x, y);
    float rx = x - __bfloat162float(H.x);
    float ry = y - __bfloat162float(H.y);
    __nv_bfloat162 L = __floats2bfloat162_rn(rx, ry);
    h = *reinterpret_cast<unsigned int*>(&H);
    l = *reinterpret_cast<unsigned int*>(&L);
}

__device__ __forceinline__ void mma_bf16(float* d, const unsigned int* a, const unsigned int* b){
    asm volatile("mma.sync.aligned.m16n8k16.row.col.f32.bf16.bf16.f32 "
        "{%0,%1,%2,%3}, {%4,%5,%6,%7}, {%8,%9}, {%0,%1,%2,%3};"
        : "+f"(d[0]),"+f"(d[1]),"+f"(d[2]),"+f"(d[3])
        : "r"(a[0]),"r"(a[1]),"r"(a[2]),"r"(a[3]), "r"(b[0]),"r"(b[1]));
}

// fused proj epilogue: silu gates for z/x, compact tail for the rest
__device__ __forceinline__ void write_proj(int row, int col, float v){
    if (col < 1024){
        g_zsilu[row*1024 + col] = v / (1.f + expf(-v));
    } else if (col < 2048){
        g_xsilu[row*1024 + col - 1024] = v / (1.f + expf(-v));
    } else {
        g_tail[row*TAILW + col - 2048] = v;
    }
}

// ---------------- tensor-core GEMM: C = A[MxK]@B[KxN] (+bias), 3x bf16 split ----------------
// block 128 x BN, BK=16, 8 warps as 2m x 4n, double-buffered, 2 CTA/SM.
// MODE 0: plain write to C.  MODE 1: fused mamba proj epilogue (C unused).
template<int BN, int MODE>
__global__ __launch_bounds__(256, 2) void k_gemm_bf16s(
    int M, int N, int K,
    const float* __restrict__ A,
    const float* __restrict__ B,
    const float* __restrict__ bias,
    float* __restrict__ C)
{
    const int BM=128;
    const int WN  = BN/4;      // warp n extent
    const int JW  = WN/8;      // n-subtiles (8 cols) per warp
    const int NB4 = BN/4;      // B staging col4 groups
    const int NBITEMS = 8*NB4;

    __shared__ unsigned int Ah[2][8][BM+8];
    __shared__ unsigned int Al[2][8][BM+8];
    __shared__ unsigned int Bh[2][8][BN+8];
    __shared__ unsigned int Bl[2][8][BN+8];

    const int tid  = threadIdx.x;
    const int lane = tid & 31;
    const int warp = tid >> 5;
    const int warpM = warp >> 2;       // 0..1 -> 64 rows each
    const int warpN = warp & 3;        // 0..3 -> WN cols each
    const int rowBase = blockIdx.y * BM;
    const int colBase = blockIdx.x * BN;
    const int kq = lane & 3;

    float acc[4][JW][4];
#pragma unroll
    for (int t=0;t<4;t++)
#pragma unroll
        for (int j=0;j<JW;j++)
#pragma unroll
            for (int q=0;q<4;q++) acc[t][j][q]=0.f;

    const int ar0 = tid >> 2;          // 0..63
    const int ac0 = (tid & 3) * 4;     // 0,4,8,12
    const int br2 = tid / NB4;
    const int bcc = (tid % NB4) * 4;
    const bool bact = (tid < NBITEMS);

    float4 pa0, pa1, pb0, pb1;

#define LOADT(kk0) { \
    pa0 = *(const float4*)&A[(size_t)(rowBase+ar0   )*K + (kk0) + ac0]; \
    pa1 = *(const float4*)&A[(size_t)(rowBase+ar0+64)*K + (kk0) + ac0]; \
    if (bact){ int gc = colBase + bcc; \
        if (gc < N){ \
            pb0 = *(const float4*)&B[(size_t)((kk0)+2*br2  )*N + gc]; \
            pb1 = *(const float4*)&B[(size_t)((kk0)+2*br2+1)*N + gc]; \
        } else { pb0 = make_float4(0,0,0,0); pb1 = pb0; } } }

#define STORET(bb) { \
    split2(pa0.x, pa0.y, Ah[bb][ac0/2  ][ar0   ], Al[bb][ac0/2  ][ar0   ]); \
    split2(pa0.z, pa0.w, Ah[bb][ac0/2+1][ar0   ], Al[bb][ac0/2+1][ar0   ]); \
    split2(pa1.x, pa1.y, Ah[bb][ac0/2  ][ar0+64], Al[bb][ac0/2  ][ar0+64]); \
    split2(pa1.z, pa1.w, Ah[bb][ac0/2+1][ar0+64], Al[bb][ac0/2+1][ar0+64]); \
    if (bact){ \
        split2(pb0.x, pb1.x, Bh[bb][br2][bcc+0], Bl[bb][br2][bcc+0]); \
        split2(pb0.y, pb1.y, Bh[bb][br2][bcc+1], Bl[bb][br2][bcc+1]); \
        split2(pb0.z, pb1.z, Bh[bb][br2][bcc+2], Bl[bb][br2][bcc+2]); \
        split2(pb0.w, pb1.w, Bh[bb][br2][bcc+3], Bl[bb][br2][bcc+3]); } }

    LOADT(0);
    STORET(0);
    __syncthreads();

    int cur = 0;
    for (int k0=0; k0<K; k0+=16){
        const bool more = (k0+16 < K);
        if (more){ LOADT(k0+16); }

        unsigned int ah[4][4], alr[4][4];
#pragma unroll
        for (int t=0;t<4;t++){
            int r = warpM*64 + t*16 + (lane>>2);
            ah[t][0]=Ah[cur][kq  ][r];   alr[t][0]=Al[cur][kq  ][r];
            ah[t][1]=Ah[cur][kq  ][r+8]; alr[t][1]=Al[cur][kq  ][r+8];
            ah[t][2]=Ah[cur][kq+4][r];   alr[t][2]=Al[cur][kq+4][r];
            ah[t][3]=Ah[cur][kq+4][r+8]; alr[t][3]=Al[cur][kq+4][r+8];
        }
        unsigned int bh[JW][2], blr[JW][2];
#pragma unroll
        for (int j=0;j<JW;j++){
            int cb = warpN*WN + j*8 + (lane>>2);
            bh[j][0]=Bh[cur][kq  ][cb];  blr[j][0]=Bl[cur][kq  ][cb];
            bh[j][1]=Bh[cur][kq+4][cb];  blr[j][1]=Bl[cur][kq+4][cb];
        }
#pragma unroll
        for (int t=0;t<4;t++)
#pragma unroll
            for (int j=0;j<JW;j++){
                mma_bf16(acc[t][j], ah[t],  bh[j]);
                mma_bf16(acc[t][j], ah[t],  blr[j]);
                mma_bf16(acc[t][j], alr[t], bh[j]);
            }
        if (more){ STORET(cur^1); }
        __syncthreads();
        cur ^= 1;
    }

    // epilogue
#pragma unroll
    for (int t=0;t<4;t++){
#pragma unroll
        for (int j=0;j<JW;j++){
            int row = rowBase + warpM*64 + t*16 + (lane>>2);
            int col = colBase + warpN*WN + j*8 + 2*(lane&3);
            float b0 = (bias && col   < N) ? bias[col]   : 0.f;
            float b1 = (bias && col+1 < N) ? bias[col+1] : 0.f;
            if (MODE == 0){
                if (col < N){
                    C[(size_t)row*N + col] = acc[t][j][0] + b0;
                    if (col+1 < N) C[(size_t)row*N + col+1] = acc[t][j][1] + b1;
                    C[(size_t)(row+8)*N + col] = acc[t][j][2] + b0;
                    if (col+1 < N) C[(size_t)(row+8)*N + col+1] = acc[t][j][3] + b1;
                }
            } else {
                if (col < N){
                    write_proj(row,   col,   acc[t][j][0] + b0);
                    write_proj(row+8, col,   acc[t][j][2] + b0);
                    if (col+1 < N){
                        write_proj(row,   col+1, acc[t][j][1] + b1);
                        write_proj(row+8, col+1, acc[t][j][3] + b1);
                    }
                }
            }
        }
    }
#undef LOADT
#undef STORET
}

// ---------------- postprocess (tail only): RMSNorm B/C, dt/lam/decay ----------------
__global__ void k_post(const float* __restrict__ wB, const float* __restrict__ wC,
                       const float* __restrict__ biasB, const float* __restrict__ biasC,
                       const float* __restrict__ A_log)
{
    const int l = blockIdx.x;
    const int tid = threadIdx.x;         // 256 threads
    const float* row = g_tail + (size_t)l*TAILW;

    __shared__ float pB[8], pC[8];
    float vB = row[tid];
    float vC = row[256+tid];
    float sB = vB*vB, sC = vC*vC;
#pragma unroll
    for (int o=16;o>0;o>>=1){
        sB += __shfl_xor_sync(0xffffffffu, sB, o);
        sC += __shfl_xor_sync(0xffffffffu, sC, o);
    }
    int wp = tid >> 5;
    if ((tid & 31) == 0){ pB[wp]=sB; pC[wp]=sC; }
    __syncthreads();

    int g = tid >> 6, j = tid & 63;
    float mB = (pB[2*g]+pB[2*g+1]) * (1.f/64.f);
    float mC = (pC[2*g]+pC[2*g+1]) * (1.f/64.f);
    g_Bm[l*256+tid] = vB * rsqrtf(mB + EPSV) * wB[j] + biasB[tid];
    g_Cm[l*256+tid] = vC * rsqrtf(mC + EPSV) * wC[j] + biasC[tid];

    if (tid < GN){
        float dtr = row[512+tid];
        float dt  = (dtr > 20.f) ? dtr : log1pf(expf(dtr));
        float lam = 1.f/(1.f+expf(-row[516+tid]));
        float A   = -expf(A_log[tid]);
        g_scal[l*GN+tid] = make_float4(dt, lam, expf(dt*A), 0.f);
    }
}

// ---------------- dt cumsum (4 sequences of 2048) + per-chunk decays ----------------
__global__ void k_scan_dt(const float* __restrict__ A_log)
{
    int g = threadIdx.x >> 5;
    int lane = threadIdx.x & 31;
    float carry = 0.f;
    for (int b=0;b<64;b++){
        int l = b*32 + lane;
        float v = g_scal[l*GN+g].x;
#pragma unroll
        for (int o=1;o<32;o<<=1){
            float t = __shfl_up_sync(0xffffffffu, v, o);
            if (lane >= o) v += t;
        }
        g_sdt[l*GN+g] = carry + v;
        carry += __shfl_sync(0xffffffffu, v, 31);
    }
    __syncthreads();
    int t = threadIdx.x;
    if (t < NC*GN){
        int c = t >> 2, gg = t & 3;
        float A = -expf(A_log[gg]);
        float e = g_sdt[(c*CH + CH-1)*GN + gg];
        float s = c ? g_sdt[(c*CH - 1)*GN + gg] : 0.f;
        g_Dc[t] = expf(A*(e-s));
    }
}

// ---------------- RoPE applied in-place to Bm, Cm ----------------
__global__ void k_rope(const float* __restrict__ theta_log)
{
    int idx = blockIdx.x*256 + threadIdx.x;
    if (idx >= LSEQ*GN*16) return;
    int j = idx & 15;
    int g = (idx >> 4) & 3;
    int l = idx >> 6;
    float th = expf(theta_log[g*16+j]);
    float ang = g_sdt[l*GN+g] * th;
    float cs = cosf(ang), sn = sinf(ang);
    int base = l*256 + g*64 + j*4;
#pragma unroll
    for (int r=0;r<2;r++){
        float re = g_Bm[base+r],   im = g_Bm[base+2+r];
        g_Bm[base+r]   = re*cs - im*sn;
        g_Bm[base+2+r] = re*sn + im*cs;
        float re2 = g_Cm[base+r],  im2 = g_Cm[base+2+r];
        g_Cm[base+r]   = re2*cs - im2*sn;
        g_Cm[base+2+r] = re2*sn + im2*cs;
    }
}

// ---------------- x_up = xsilu[L*H,64] @ W_xup[64,128], 64 rows/block ----------------
__global__ __launch_bounds__(256) void k_xup(const float* __restrict__ Wx)
{
    __shared__ float Ws[64][128];
    __shared__ float Xs[64][64];
    int tid = threadIdx.x;  // 256
    for (int i=tid;i<64*128;i+=256) Ws[i>>7][i&127] = Wx[i];
    int m0 = blockIdx.x*64;
    for (int i=tid;i<64*64;i+=256)  Xs[i>>6][i&63]  = g_xsilu[(size_t)(m0 + (i>>6))*64 + (i&63)];
    __syncthreads();
    int col = (tid & 31)*4;
    int rb  = (tid >> 5)*8;            // 8 rows per thread
    float a[8][4];
#pragma unroll
    for (int i=0;i<8;i++)
#pragma unroll
        for (int q=0;q<4;q++) a[i][q]=0.f;
#pragma unroll 2
    for (int k=0;k<64;k++){
        float4 w = *(const float4*)&Ws[k][col];
#pragma unroll
        for (int i=0;i<8;i++){
            float x = Xs[rb+i][k];
            a[i][0]+=x*w.x; a[i][1]+=x*w.y; a[i][2]+=x*w.z; a[i][3]+=x*w.w;
        }
    }
#pragma unroll
    for (int i=0;i<8;i++)
        *(float4*)&g_xup[(size_t)(m0+rb+i)*128 + col] = make_float4(a[i][0],a[i][1],a[i][2],a[i][3]);
}

// ---------------- pass A: chunk-local scan, emit final states ----------------
__global__ void k_passA()
{
    const int c = blockIdx.z, h = blockIdx.y;
    const int p = blockIdx.x*4 + (threadIdx.x >> 5);
    const int n = threadIdx.x & 31;
    const int g = h >> 2;
    const int t0 = c*CH;

    float u_prev = 0.f;
    if (c){
        int t = t0-1;
        float2 B = *(const float2*)&g_Bm[(t*GN+g)*64 + n*2];
        float2 X = *(const float2*)&g_xup[(size_t)(t*HH+h)*128 + p*2];
        float4 s = g_scal[t*GN+g];
        u_prev = s.x*(B.x*X.x + B.y*X.y);
    }
    float hs = 0.f;
#pragma unroll 4
    for (int t=t0; t<t0+CH; t++){
        float2 B = *(const float2*)&g_Bm[(t*GN+g)*64 + n*2];
        float2 X = *(const float2*)&g_xup[(size_t)(t*HH+h)*128 + p*2];
        float4 s = g_scal[t*GN+g];
        float uss = s.x*(B.x*X.x + B.y*X.y);
        float ut  = s.y*uss + (1.f-s.y)*u_prev;
        u_prev = uss;
        hs = hs*s.z + ut;
    }
    g_F[((c*HH+h)*PP+p)*NS + n] = hs;
}

// ---------------- pass B: inter-chunk combine (16-step scan) ----------------
__global__ void k_passB()
{
    int gw = blockIdx.x*8 + (threadIdx.x >> 5);   // 1024 warps total
    int n  = threadIdx.x & 31;
    int h = gw >> 6, p = gw & 63;
    int g = h >> 2;
    float S = 0.f;
#pragma unroll
    for (int c=0;c<NC;c++){
        int idx = ((c*HH+h)*PP+p)*NS + n;
        g_S[idx] = S;
        S = S*g_Dc[c*GN+g] + g_F[idx];
    }
}

// ---------------- pass C: rescan with incoming state, produce y_raw ----------------
__global__ void k_passC()
{
    const int c = blockIdx.z, h = blockIdx.y;
    const int p = blockIdx.x*4 + (threadIdx.x >> 5);
    const int n = threadIdx.x & 31;
    const int g = h >> 2;
    const int t0 = c*CH;

    float u_prev = 0.f;
    if (c){
        int t = t0-1;
        float2 B = *(const float2*)&g_Bm[(t*GN+g)*64 + n*2];
        float2 X = *(const float2*)&g_xup[(size_t)(t*HH+h)*128 + p*2];
        float4 s = g_scal[t*GN+g];
        u_prev = s.x*(B.x*X.x + B.y*X.y);
    }
    float hs = g_S[((c*HH+h)*PP+p)*NS + n];
    const bool isLane0  = (n == 0);
    const bool isLane16 = (n == 16);
    const bool low = (n < 16);
#pragma unroll 2
    for (int t=t0; t<t0+CH; t++){
        float2 B = *(const float2*)&g_Bm[(t*GN+g)*64 + n*2];
        float2 X = *(const float2*)&g_xup[(size_t)(t*HH+h)*128 + p*2];
        float4 s = g_scal[t*GN+g];
        float uss = s.x*(B.x*X.x + B.y*X.y);
        float ut  = s.y*uss + (1.f-s.y)*u_prev;
        u_prev = uss;
        hs = hs*s.z + ut;

        float2 Cv = *(const float2*)&g_Cm[(t*GN+g)*64 + n*2];
        float y0 = hs*Cv.x, y1 = hs*Cv.y;
        float t0s = __shfl_xor_sync(0xffffffffu, y0, 16);
        float t1s = __shfl_xor_sync(0xffffffffu, y1, 16);
        float v = low ? (y0 + t0s) : (y1 + t1s);
#pragma unroll
        for (int o=8;o>0;o>>=1) v += __shfl_xor_sync(0xffffffffu, v, o);
        float* dst = &g_yraw[(size_t)(t*HH+h)*128 + p*2];
        if (isLane0)  dst[0] = v;
        if (isLane16) dst[1] = v;
    }
}

// ---------------- ydown + skip + z-gate ----------------
__global__ void k_ydown(const float* __restrict__ Wy, const float* __restrict__ Dp)
{
    __shared__ float Ws[128][64];
    __shared__ float Ys[16][128];
    int tid = threadIdx.x;  // 128
    for (int i=tid;i<128*64;i+=128) Ws[i>>6][i&63]  = Wy[i];
    int m0 = blockIdx.x*16;
    for (int i=tid;i<16*128;i+=128) Ys[i>>7][i&127] = g_yraw[(size_t)(m0 + (i>>7))*128 + (i&127)];
    __syncthreads();
    int col = (tid & 15)*4;
    int r0  = (tid >> 4)*2;
    float a0c[4]={0,0,0,0}, a1c[4]={0,0,0,0};
#pragma unroll 4
    for (int k=0;k<128;k++){
        float a0 = Ys[r0][k], a1 = Ys[r0+1][k];
        float4 w = *(const float4*)&Ws[k][col];
        a0c[0]+=a0*w.x; a0c[1]+=a0*w.y; a0c[2]+=a0*w.z; a0c[3]+=a0*w.w;
        a1c[0]+=a1*w.x; a1c[1]+=a1*w.y; a1c[2]+=a1*w.z; a1c[3]+=a1*w.w;
    }
#pragma unroll
    for (int rr=0;rr<2;rr++){
        int m = m0 + r0 + rr;
        int hh = m & 15;
        float dv = Dp[hh];
        float* accp = rr ? a1c : a0c;
#pragma unroll
        for (int j2=0;j2<4;j2++){
            int o = m*64 + col + j2;
            float v = accp[j2] + dv * g_xsilu[o];
            g_y3[o] = v * g_zsilu[o];
        }
    }
}

// ---------------- launch ----------------
extern "C" void kernel_launch(void* const* d_in, const int* in_sizes, int n_in,
                              void* d_out, int out_size)
{
    const float* u        = (const float*)d_in[0];
    const float* W_in     = (const float*)d_in[1];
    const float* b_in     = (const float*)d_in[2];
    const float* W_xup    = (const float*)d_in[3];
    const float* W_ydown  = (const float*)d_in[4];
    const float* A_log    = (const float*)d_in[5];
    const float* theta_log= (const float*)d_in[6];
    const float* D_param  = (const float*)d_in[7];
    const float* wB       = (const float*)d_in[8];
    const float* wC       = (const float*)d_in[9];
    const float* bias_B   = (const float*)d_in[10];
    const float* bias_C   = (const float*)d_in[11];
    const float* W_out    = (const float*)d_in[12];
    float* out = (float*)d_out;

    float *p_y3;
    cudaGetSymbolAddress((void**)&p_y3, g_y3);

    // 1. proj = u @ W_in + b_in  [2048 x 2568, K=512], fused silu/tail epilogue
    {
        dim3 grid((DPROJ + 127)/128, LSEQ/128);
        k_gemm_bf16s<128,1><<<grid, 256>>>(LSEQ, DPROJ, DMODEL, u, W_in, b_in, nullptr);
    }
    // 2. rmsnorm B/C + dt/lam (tail only)
    k_post<<<LSEQ, 256>>>(wB, wC, bias_B, bias_C, A_log);
    // 3. dt cumsum + chunk decays
    k_scan_dt<<<1, 128>>>(A_log);
    // 4. RoPE
    k_rope<<<(LSEQ*GN*16 + 255)/256, 256>>>(theta_log);
    // 5. x_up
    k_xup<<<(LSEQ*HH)/64, 256>>>(W_xup);
    // 6-8. chunked recurrence
    k_passA<<<dim3(16, HH, NC), 128>>>();
    k_passB<<<128, 256>>>();
    k_passC<<<dim3(16, HH, NC), 128>>>();
    // 9. ydown + skip + gate
    k_ydown<<<(LSEQ*HH)/16, 128>>>(W_ydown, D_param);
    // 10. out = y3 @ W_out  [2048 x 512, K=1024], BN=32 for full-chip spread
    {
        dim3 grid(DMODEL/32, LSEQ/128);
        k_gemm_bf16s<32,0><<<grid, 256>>>(LSEQ, DMODEL, 1024, p_y3, W_out, nullptr, out);
    }
}

// round 15
// speedup vs baseline: 1.0446x; 1.0446x over previous
#include <cuda_runtime.h>
#include <cuda_bf16.h>
#include <cstdint>

// ---------------- problem dims ----------------
#define LSEQ 2048
#define DMODEL 512
#define DPROJ 2568
#define GN 4          // groups
#define NS 32         // d_state
#define HH 16         // heads
#define PP 64         // head dim
#define NC 16         // chunks
#define CH 128        // chunk len
#define EPSV 1e-5f
#define TAILW 520     // B(256) C(256) dt(4) lam(4)

// ---------------- scratch (device globals; no allocs allowed) ----------------
__device__ float  g_tail [LSEQ*TAILW];        // compact proj tail
__device__ float  g_zsilu[LSEQ*1024];
__device__ float  g_xsilu[LSEQ*1024];
__device__ float  g_Bm   [LSEQ*GN*64];
__device__ float  g_Cm   [LSEQ*GN*64];
__device__ float4 g_scal [LSEQ*GN];           // (dt, lam, decay, 0)
__device__ float  g_sdt  [LSEQ*GN];
__device__ float  g_Dc   [NC*GN];
__device__ float  g_xup  [LSEQ*HH*128];
__device__ float  g_F    [NC*HH*PP*NS];
__device__ float  g_S    [NC*HH*PP*NS];
__device__ float  g_yraw [LSEQ*HH*128];
__device__ float  g_y3   [LSEQ*1024];

// ---------------- bf16-split helpers ----------------
__device__ __forceinline__ void split2(float x, float y, unsigned int& h, unsigned int& l){
    __nv_bfloat162 H = __floats2bfloat162_rn(x, y);
    float rx = x - __bfloat162float(H.x);
    float ry = y - __bfloat162float(H.y);
    __nv_bfloat162 L = __floats2bfloat162_rn(rx, ry);
    h = *reinterpret_cast<unsigned int*>(&H);
    l = *reinterpret_cast<unsigned int*>(&L);
}

__device__ __forceinline__ void mma_bf16(float* d, const unsigned int* a, const unsigned int* b){
    asm volatile("mma.sync.aligned.m16n8k16.row.col.f32.bf16.bf16.f32 "
        "{%0,%1,%2,%3}, {%4,%5,%6,%7}, {%8,%9}, {%0,%1,%2,%3};"
        : "+f"(d[0]),"+f"(d[1]),"+f"(d[2]),"+f"(d[3])
        : "r"(a[0]),"r"(a[1]),"r"(a[2]),"r"(a[3]), "r"(b[0]),"r"(b[1]));
}

// fused proj epilogue: silu gates for z/x, compact tail for the rest
__device__ __forceinline__ void write_proj(int row, int col, float v){
    if (col < 1024){
        g_zsilu[row*1024 + col] = v / (1.f + expf(-v));
    } else if (col < 2048){
        g_xsilu[row*1024 + col - 1024] = v / (1.f + expf(-v));
    } else {
        g_tail[row*TAILW + col - 2048] = v;
    }
}

// ---------------- tensor-core GEMM: C = A[MxK]@B[KxN] (+bias), 3x bf16 split ----------------
// block 128 x BN, BK=16, 8 warps as 2m x 4n, double-buffered, 2 CTA/SM.
// MODE 0: plain write to C.  MODE 1: fused mamba proj epilogue (C unused).
template<int BN, int MODE>
__global__ __launch_bounds__(256, 2) void k_gemm_bf16s(
    int M, int N, int K,
    const float* __restrict__ A,
    const float* __restrict__ B,
    const float* __restrict__ bias,
    float* __restrict__ C)
{
    const int BM=128;
    const int WN  = BN/4;      // warp n extent
    const int JW  = WN/8;      // n-subtiles (8 cols) per warp
    const int NB4 = BN/4;      // B staging col4 groups
    const int NBITEMS = 8*NB4;

    __shared__ unsigned int Ah[2][8][BM+8];
    __shared__ unsigned int Al[2][8][BM+8];
    __shared__ unsigned int Bh[2][8][BN+8];
    __shared__ unsigned int Bl[2][8][BN+8];

    const int tid  = threadIdx.x;
    const int lane = tid & 31;
    const int warp = tid >> 5;
    const int warpM = warp >> 2;       // 0..1 -> 64 rows each
    const int warpN = warp & 3;        // 0..3 -> WN cols each
    const int rowBase = blockIdx.y * BM;
    const int colBase = blockIdx.x * BN;
    const int kq = lane & 3;

    float acc[4][JW][4];
#pragma unroll
    for (int t=0;t<4;t++)
#pragma unroll
        for (int j=0;j<JW;j++)
#pragma unroll
            for (int q=0;q<4;q++) acc[t][j][q]=0.f;

    const int ar0 = tid >> 2;          // 0..63
    const int ac0 = (tid & 3) * 4;     // 0,4,8,12
    const int br2 = tid / NB4;
    const int bcc = (tid % NB4) * 4;
    const bool bact = (tid < NBITEMS);

    float4 pa0, pa1, pb0, pb1;

#define LOADT(kk0) { \
    pa0 = *(const float4*)&A[(size_t)(rowBase+ar0   )*K + (kk0) + ac0]; \
    pa1 = *(const float4*)&A[(size_t)(rowBase+ar0+64)*K + (kk0) + ac0]; \
    if (bact){ int gc = colBase + bcc; \
        if (gc < N){ \
            pb0 = *(const float4*)&B[(size_t)((kk0)+2*br2  )*N + gc]; \
            pb1 = *(const float4*)&B[(size_t)((kk0)+2*br2+1)*N + gc]; \
        } else { pb0 = make_float4(0,0,0,0); pb1 = pb0; } } }

#define STORET(bb) { \
    split2(pa0.x, pa0.y, Ah[bb][ac0/2  ][ar0   ], Al[bb][ac0/2  ][ar0   ]); \
    split2(pa0.z, pa0.w, Ah[bb][ac0/2+1][ar0   ], Al[bb][ac0/2+1][ar0   ]); \
    split2(pa1.x, pa1.y, Ah[bb][ac0/2  ][ar0+64], Al[bb][ac0/2  ][ar0+64]); \
    split2(pa1.z, pa1.w, Ah[bb][ac0/2+1][ar0+64], Al[bb][ac0/2+1][ar0+64]); \
    if (bact){ \
        split2(pb0.x, pb1.x, Bh[bb][br2][bcc+0], Bl[bb][br2][bcc+0]); \
        split2(pb0.y, pb1.y, Bh[bb][br2][bcc+1], Bl[bb][br2][bcc+1]); \
        split2(pb0.z, pb1.z, Bh[bb][br2][bcc+2], Bl[bb][br2][bcc+2]); \
        split2(pb0.w, pb1.w, Bh[bb][br2][bcc+3], Bl[bb][br2][bcc+3]); } }

    LOADT(0);
    STORET(0);
    __syncthreads();

    int cur = 0;
    for (int k0=0; k0<K; k0+=16){
        const bool more = (k0+16 < K);
        if (more){ LOADT(k0+16); }

        unsigned int ah[4][4], alr[4][4];
#pragma unroll
        for (int t=0;t<4;t++){
            int r = warpM*64 + t*16 + (lane>>2);
            ah[t][0]=Ah[cur][kq  ][r];   alr[t][0]=Al[cur][kq  ][r];
            ah[t][1]=Ah[cur][kq  ][r+8]; alr[t][1]=Al[cur][kq  ][r+8];
            ah[t][2]=Ah[cur][kq+4][r];   alr[t][2]=Al[cur][kq+4][r];
            ah[t][3]=Ah[cur][kq+4][r+8]; alr[t][3]=Al[cur][kq+4][r+8];
        }
        unsigned int bh[JW][2], blr[JW][2];
#pragma unroll
        for (int j=0;j<JW;j++){
            int cb = warpN*WN + j*8 + (lane>>2);
            bh[j][0]=Bh[cur][kq  ][cb];  blr[j][0]=Bl[cur][kq  ][cb];
            bh[j][1]=Bh[cur][kq+4][cb];  blr[j][1]=Bl[cur][kq+4][cb];
        }
#pragma unroll
        for (int t=0;t<4;t++)
#pragma unroll
            for (int j=0;j<JW;j++){
                mma_bf16(acc[t][j], ah[t],  bh[j]);
                mma_bf16(acc[t][j], ah[t],  blr[j]);
                mma_bf16(acc[t][j], alr[t], bh[j]);
            }
        if (more){ STORET(cur^1); }
        __syncthreads();
        cur ^= 1;
    }

    // epilogue
#pragma unroll
    for (int t=0;t<4;t++){
#pragma unroll
        for (int j=0;j<JW;j++){
            int row = rowBase + warpM*64 + t*16 + (lane>>2);
            int col = colBase + warpN*WN + j*8 + 2*(lane&3);
            float b0 = (bias && col   < N) ? bias[col]   : 0.f;
            float b1 = (bias && col+1 < N) ? bias[col+1] : 0.f;
            if (MODE == 0){
                if (col < N){
                    C[(size_t)row*N + col] = acc[t][j][0] + b0;
                    if (col+1 < N) C[(size_t)row*N + col+1] = acc[t][j][1] + b1;
                    C[(size_t)(row+8)*N + col] = acc[t][j][2] + b0;
                    if (col+1 < N) C[(size_t)(row+8)*N + col+1] = acc[t][j][3] + b1;
                }
            } else {
                if (col < N){
                    write_proj(row,   col,   acc[t][j][0] + b0);
                    write_proj(row+8, col,   acc[t][j][2] + b0);
                    if (col+1 < N){
                        write_proj(row,   col+1, acc[t][j][1] + b1);
                        write_proj(row+8, col+1, acc[t][j][3] + b1);
                    }
                }
            }
        }
    }
#undef LOADT
#undef STORET
}

// ---------------- postprocess (tail only): RMSNorm B/C, dt/lam/decay ----------------
__global__ void k_post(const float* __restrict__ wB, const float* __restrict__ wC,
                       const float* __restrict__ biasB, const float* __restrict__ biasC,
                       const float* __restrict__ A_log)
{
    const int l = blockIdx.x;
    const int tid = threadIdx.x;         // 256 threads
    const float* row = g_tail + (size_t)l*TAILW;

    __shared__ float pB[8], pC[8];
    float vB = row[tid];
    float vC = row[256+tid];
    float sB = vB*vB, sC = vC*vC;
#pragma unroll
    for (int o=16;o>0;o>>=1){
        sB += __shfl_xor_sync(0xffffffffu, sB, o);
        sC += __shfl_xor_sync(0xffffffffu, sC, o);
    }
    int wp = tid >> 5;
    if ((tid & 31) == 0){ pB[wp]=sB; pC[wp]=sC; }
    __syncthreads();

    int g = tid >> 6, j = tid & 63;
    float mB = (pB[2*g]+pB[2*g+1]) * (1.f/64.f);
    float mC = (pC[2*g]+pC[2*g+1]) * (1.f/64.f);
    g_Bm[l*256+tid] = vB * rsqrtf(mB + EPSV) * wB[j] + biasB[tid];
    g_Cm[l*256+tid] = vC * rsqrtf(mC + EPSV) * wC[j] + biasC[tid];

    if (tid < GN){
        float dtr = row[512+tid];
        float dt  = (dtr > 20.f) ? dtr : log1pf(expf(dtr));
        float lam = 1.f/(1.f+expf(-row[516+tid]));
        float A   = -expf(A_log[tid]);
        g_scal[l*GN+tid] = make_float4(dt, lam, expf(dt*A), 0.f);
    }
}

// ---------------- dt cumsum (4 sequences of 2048) + per-chunk decays ----------------
__global__ void k_scan_dt(const float* __restrict__ A_log)
{
    int g = threadIdx.x >> 5;
    int lane = threadIdx.x & 31;
    float carry = 0.f;
    for (int b=0;b<64;b++){
        int l = b*32 + lane;
        float v = g_scal[l*GN+g].x;
#pragma unroll
        for (int o=1;o<32;o<<=1){
            float t = __shfl_up_sync(0xffffffffu, v, o);
            if (lane >= o) v += t;
        }
        g_sdt[l*GN+g] = carry + v;
        carry += __shfl_sync(0xffffffffu, v, 31);
    }
    __syncthreads();
    int t = threadIdx.x;
    if (t < NC*GN){
        int c = t >> 2, gg = t & 3;
        float A = -expf(A_log[gg]);
        float e = g_sdt[(c*CH + CH-1)*GN + gg];
        float s = c ? g_sdt[(c*CH - 1)*GN + gg] : 0.f;
        g_Dc[t] = expf(A*(e-s));
    }
}

// ---------------- RoPE applied in-place to Bm, Cm ----------------
__global__ void k_rope(const float* __restrict__ theta_log)
{
    int idx = blockIdx.x*256 + threadIdx.x;
    if (idx >= LSEQ*GN*16) return;
    int j = idx & 15;
    int g = (idx >> 4) & 3;
    int l = idx >> 6;
    float th = expf(theta_log[g*16+j]);
    float ang = g_sdt[l*GN+g] * th;
    float cs = cosf(ang), sn = sinf(ang);
    int base = l*256 + g*64 + j*4;
#pragma unroll
    for (int r=0;r<2;r++){
        float re = g_Bm[base+r],   im = g_Bm[base+2+r];
        g_Bm[base+r]   = re*cs - im*sn;
        g_Bm[base+2+r] = re*sn + im*cs;
        float re2 = g_Cm[base+r],  im2 = g_Cm[base+2+r];
        g_Cm[base+r]   = re2*cs - im2*sn;
        g_Cm[base+2+r] = re2*sn + im2*cs;
    }
}

// ---------------- x_up = xsilu[L*H,64] @ W_xup[64,128], 64 rows/block ----------------
__global__ __launch_bounds__(256) void k_xup(const float* __restrict__ Wx)
{
    __shared__ float Ws[64][128];
    __shared__ float Xs[64][64];
    int tid = threadIdx.x;  // 256
    for (int i=tid;i<64*128;i+=256) Ws[i>>7][i&127] = Wx[i];
    int m0 = blockIdx.x*64;
    for (int i=tid;i<64*64;i+=256)  Xs[i>>6][i&63]  = g_xsilu[(size_t)(m0 + (i>>6))*64 + (i&63)];
    __syncthreads();
    int col = (tid & 31)*4;
    int rb  = (tid >> 5)*8;            // 8 rows per thread
    float a[8][4];
#pragma unroll
    for (int i=0;i<8;i++)
#pragma unroll
        for (int q=0;q<4;q++) a[i][q]=0.f;
#pragma unroll 2
    for (int k=0;k<64;k++){
        float4 w = *(const float4*)&Ws[k][col];
#pragma unroll
        for (int i=0;i<8;i++){
            float x = Xs[rb+i][k];
            a[i][0]+=x*w.x; a[i][1]+=x*w.y; a[i][2]+=x*w.z; a[i][3]+=x*w.w;
        }
    }
#pragma unroll
    for (int i=0;i<8;i++)
        *(float4*)&g_xup[(size_t)(m0+rb+i)*128 + col] = make_float4(a[i][0],a[i][1],a[i][2],a[i][3]);
}

// ---------------- pass A: chunk-local scan, emit final states ----------------
__global__ void k_passA()
{
    const int c = blockIdx.z, h = blockIdx.y;
    const int p = blockIdx.x*4 + (threadIdx.x >> 5);
    const int n = threadIdx.x & 31;
    const int g = h >> 2;
    const int t0 = c*CH;

    float u_prev = 0.f;
    if (c){
        int t = t0-1;
        float2 B = *(const float2*)&g_Bm[(t*GN+g)*64 + n*2];
        float2 X = *(const float2*)&g_xup[(size_t)(t*HH+h)*128 + p*2];
        float4 s = g_scal[t*GN+g];
        u_prev = s.x*(B.x*X.x + B.y*X.y);
    }
    float hs = 0.f;
#pragma unroll 4
    for (int t=t0; t<t0+CH; t++){
        float2 B = *(const float2*)&g_Bm[(t*GN+g)*64 + n*2];
        float2 X = *(const float2*)&g_xup[(size_t)(t*HH+h)*128 + p*2];
        float4 s = g_scal[t*GN+g];
        float uss = s.x*(B.x*X.x + B.y*X.y);
        float ut  = s.y*uss + (1.f-s.y)*u_prev;
        u_prev = uss;
        hs = hs*s.z + ut;
    }
    g_F[((c*HH+h)*PP+p)*NS + n] = hs;
}

// ---------------- pass B: inter-chunk combine (16-step scan) ----------------
__global__ void k_passB()
{
    int gw = blockIdx.x*8 + (threadIdx.x >> 5);   // 1024 warps total
    int n  = threadIdx.x & 31;
    int h = gw >> 6, p = gw & 63;
    int g = h >> 2;
    float S = 0.f;
#pragma unroll
    for (int c=0;c<NC;c++){
        int idx = ((c*HH+h)*PP+p)*NS + n;
        g_S[idx] = S;
        S = S*g_Dc[c*GN+g] + g_F[idx];
    }
}

// ---------------- pass C: rescan with incoming state, produce y_raw ----------------
__global__ void k_passC()
{
    const int c = blockIdx.z, h = blockIdx.y;
    const int p = blockIdx.x*4 + (threadIdx.x >> 5);
    const int n = threadIdx.x & 31;
    const int g = h >> 2;
    const int t0 = c*CH;

    float u_prev = 0.f;
    if (c){
        int t = t0-1;
        float2 B = *(const float2*)&g_Bm[(t*GN+g)*64 + n*2];
        float2 X = *(const float2*)&g_xup[(size_t)(t*HH+h)*128 + p*2];
        float4 s = g_scal[t*GN+g];
        u_prev = s.x*(B.x*X.x + B.y*X.y);
    }
    float hs = g_S[((c*HH+h)*PP+p)*NS + n];
    const bool isLane0  = (n == 0);
    const bool isLane16 = (n == 16);
    const bool low = (n < 16);
#pragma unroll 2
    for (int t=t0; t<t0+CH; t++){
        float2 B = *(const float2*)&g_Bm[(t*GN+g)*64 + n*2];
        float2 X = *(const float2*)&g_xup[(size_t)(t*HH+h)*128 + p*2];
        float4 s = g_scal[t*GN+g];
        float uss = s.x*(B.x*X.x + B.y*X.y);
        float ut  = s.y*uss + (1.f-s.y)*u_prev;
        u_prev = uss;
        hs = hs*s.z + ut;

        float2 Cv = *(const float2*)&g_Cm[(t*GN+g)*64 + n*2];
        float y0 = hs*Cv.x, y1 = hs*Cv.y;
        float t0s = __shfl_xor_sync(0xffffffffu, y0, 16);
        float t1s = __shfl_xor_sync(0xffffffffu, y1, 16);
        float v = low ? (y0 + t0s) : (y1 + t1s);
#pragma unroll
        for (int o=8;o>0;o>>=1) v += __shfl_xor_sync(0xffffffffu, v, o);
        float* dst = &g_yraw[(size_t)(t*HH+h)*128 + p*2];
        if (isLane0)  dst[0] = v;
        if (isLane16) dst[1] = v;
    }
}

// ---------------- ydown + skip + z-gate ----------------
__global__ void k_ydown(const float* __restrict__ Wy, const float* __restrict__ Dp)
{
    __shared__ float Ws[128][64];
    __shared__ float Ys[16][128];
    int tid = threadIdx.x;  // 128
    for (int i=tid;i<128*64;i+=128) Ws[i>>6][i&63]  = Wy[i];
    int m0 = blockIdx.x*16;
    for (int i=tid;i<16*128;i+=128) Ys[i>>7][i&127] = g_yraw[(size_t)(m0 + (i>>7))*128 + (i&127)];
    __syncthreads();
    int col = (tid & 15)*4;
    int r0  = (tid >> 4)*2;
    float a0c[4]={0,0,0,0}, a1c[4]={0,0,0,0};
#pragma unroll 4
    for (int k=0;k<128;k++){
        float a0 = Ys[r0][k], a1 = Ys[r0+1][k];
        float4 w = *(const float4*)&Ws[k][col];
        a0c[0]+=a0*w.x; a0c[1]+=a0*w.y; a0c[2]+=a0*w.z; a0c[3]+=a0*w.w;
        a1c[0]+=a1*w.x; a1c[1]+=a1*w.y; a1c[2]+=a1*w.z; a1c[3]+=a1*w.w;
    }
#pragma unroll
    for (int rr=0;rr<2;rr++){
        int m = m0 + r0 + rr;
        int hh = m & 15;
        float dv = Dp[hh];
        float* accp = rr ? a1c : a0c;
#pragma unroll
        for (int j2=0;j2<4;j2++){
            int o = m*64 + col + j2;
            float v = accp[j2] + dv * g_xsilu[o];
            g_y3[o] = v * g_zsilu[o];
        }
    }
}

// ---------------- launch ----------------
extern "C" void kernel_launch(void* const* d_in, const int* in_sizes, int n_in,
                              void* d_out, int out_size)
{
    const float* u        = (const float*)d_in[0];
    const float* W_in     = (const float*)d_in[1];
    const float* b_in     = (const float*)d_in[2];
    const float* W_xup    = (const float*)d_in[3];
    const float* W_ydown  = (const float*)d_in[4];
    const float* A_log    = (const float*)d_in[5];
    const float* theta_log= (const float*)d_in[6];
    const float* D_param  = (const float*)d_in[7];
    const float* wB       = (const float*)d_in[8];
    const float* wC       = (const float*)d_in[9];
    const float* bias_B   = (const float*)d_in[10];
    const float* bias_C   = (const float*)d_in[11];
    const float* W_out    = (const float*)d_in[12];
    float* out = (float*)d_out;

    float *p_y3;
    cudaGetSymbolAddress((void**)&p_y3, g_y3);

    // 1. proj = u @ W_in + b_in  [2048 x 2568, K=512], fused silu/tail epilogue
    {
        dim3 grid((DPROJ + 127)/128, LSEQ/128);
        k_gemm_bf16s<128,1><<<grid, 256>>>(LSEQ, DPROJ, DMODEL, u, W_in, b_in, nullptr);
    }
    // 2. rmsnorm B/C + dt/lam (tail only)
    k_post<<<LSEQ, 256>>>(wB, wC, bias_B, bias_C, A_log);
    // 3. dt cumsum + chunk decays
    k_scan_dt<<<1, 128>>>(A_log);
    // 4. RoPE
    k_rope<<<(LSEQ*GN*16 + 255)/256, 256>>>(theta_log);
    // 5. x_up
    k_xup<<<(LSEQ*HH)/64, 256>>>(W_xup);
    // 6-8. chunked recurrence
    k_passA<<<dim3(16, HH, NC), 128>>>();
    k_passB<<<128, 256>>>();
    k_passC<<<dim3(16, HH, NC), 128>>>();
    // 9. ydown + skip + gate
    k_ydown<<<(LSEQ*HH)/16, 128>>>(W_ydown, D_param);
    // 10. out = y3 @ W_out  [2048 x 512, K=1024], BN=64 (bisect revert from BN=32)
    {
        dim3 grid(DMODEL/64, LSEQ/128);
        k_gemm_bf16s<64,0><<<grid, 256>>>(LSEQ, DMODEL, 1024, p_y3, W_out, nullptr, out);
    }
}

// round 16
// speedup vs baseline: 1.1521x; 1.1029x over previous
#include <cuda_runtime.h>
#include <cuda_bf16.h>
#include <cstdint>

// ---------------- problem dims ----------------
#define LSEQ 2048
#define DMODEL 512
#define DPROJ 2568
#define GN 4          // groups
#define NS 32         // d_state
#define HH 16         // heads
#define PP 64         // head dim
#define NC 16         // chunks
#define CH 128        // chunk len
#define EPSV 1e-5f
#define TAILW 520     // B(256) C(256) dt(4) lam(4)

// ---------------- scratch (device globals; no allocs allowed) ----------------
__device__ float  g_tail [LSEQ*TAILW];        // compact proj tail
__device__ float  g_zsilu[LSEQ*1024];
__device__ float  g_xsilu[LSEQ*1024];
__device__ float  g_Bm   [LSEQ*GN*64];
__device__ float  g_Cm   [LSEQ*GN*64];
__device__ float4 g_scal [LSEQ*GN];           // (dt, lam, decay, 0)
__device__ float  g_sdt  [LSEQ*GN];
__device__ float  g_Dc   [NC*GN];
__device__ float  g_xup  [LSEQ*HH*128];
__device__ float  g_F    [NC*HH*PP*NS];
__device__ float  g_S    [NC*HH*PP*NS];
__device__ float  g_yraw [LSEQ*HH*128];
__device__ float  g_y3   [LSEQ*1024];

// ---------------- bf16-split helpers ----------------
__device__ __forceinline__ void split2(float x, float y, unsigned int& h, unsigned int& l){
    __nv_bfloat162 H = __floats2bfloat162_rn(x, y);
    float rx = x - __bfloat162float(H.x);
    float ry = y - __bfloat162float(H.y);
    __nv_bfloat162 L = __floats2bfloat162_rn(rx, ry);
    h = *reinterpret_cast<unsigned int*>(&H);
    l = *reinterpret_cast<unsigned int*>(&L);
}

__device__ __forceinline__ void mma_bf16(float* d, const unsigned int* a, const unsigned int* b){
    asm volatile("mma.sync.aligned.m16n8k16.row.col.f32.bf16.bf16.f32 "
        "{%0,%1,%2,%3}, {%4,%5,%6,%7}, {%8,%9}, {%0,%1,%2,%3};"
        : "+f"(d[0]),"+f"(d[1]),"+f"(d[2]),"+f"(d[3])
        : "r"(a[0]),"r"(a[1]),"r"(a[2]),"r"(a[3]), "r"(b[0]),"r"(b[1]));
}

// fused proj epilogue: silu gates for z/x, compact tail for the rest
__device__ __forceinline__ void write_proj(int row, int col, float v){
    if (col < 1024){
        g_zsilu[row*1024 + col] = v / (1.f + expf(-v));
    } else if (col < 2048){
        g_xsilu[row*1024 + col - 1024] = v / (1.f + expf(-v));
    } else {
        g_tail[row*TAILW + col - 2048] = v;
    }
}

// ---------------- tensor-core GEMM: C = A[MxK]@B[KxN] (+bias), 3x bf16 split ----------------
// block 128 x BN, BK=16, 8 warps as 2m x 4n, double-buffered, 2 CTA/SM.
// MODE 0: plain write to C.  MODE 1: fused mamba proj epilogue (C unused).
template<int BN, int MODE>
__global__ __launch_bounds__(256, 2) void k_gemm_bf16s(
    int M, int N, int K,
    const float* __restrict__ A,
    const float* __restrict__ B,
    const float* __restrict__ bias,
    float* __restrict__ C)
{
    const int BM=128;
    const int WN  = BN/4;      // warp n extent
    const int JW  = WN/8;      // n-subtiles (8 cols) per warp
    const int NB4 = BN/4;      // B staging col4 groups
    const int NBITEMS = 8*NB4;

    __shared__ unsigned int Ah[2][8][BM+8];
    __shared__ unsigned int Al[2][8][BM+8];
    __shared__ unsigned int Bh[2][8][BN+8];
    __shared__ unsigned int Bl[2][8][BN+8];

    const int tid  = threadIdx.x;
    const int lane = tid & 31;
    const int warp = tid >> 5;
    const int warpM = warp >> 2;       // 0..1 -> 64 rows each
    const int warpN = warp & 3;        // 0..3 -> WN cols each
    const int rowBase = blockIdx.y * BM;
    const int colBase = blockIdx.x * BN;
    const int kq = lane & 3;

    float acc[4][JW][4];
#pragma unroll
    for (int t=0;t<4;t++)
#pragma unroll
        for (int j=0;j<JW;j++)
#pragma unroll
            for (int q=0;q<4;q++) acc[t][j][q]=0.f;

    const int ar0 = tid >> 2;          // 0..63
    const int ac0 = (tid & 3) * 4;     // 0,4,8,12
    const int br2 = tid / NB4;
    const int bcc = (tid % NB4) * 4;
    const bool bact = (tid < NBITEMS);

    float4 pa0, pa1, pb0, pb1;

#define LOADT(kk0) { \
    pa0 = *(const float4*)&A[(size_t)(rowBase+ar0   )*K + (kk0) + ac0]; \
    pa1 = *(const float4*)&A[(size_t)(rowBase+ar0+64)*K + (kk0) + ac0]; \
    if (bact){ int gc = colBase + bcc; \
        if (gc < N){ \
            pb0 = *(const float4*)&B[(size_t)((kk0)+2*br2  )*N + gc]; \
            pb1 = *(const float4*)&B[(size_t)((kk0)+2*br2+1)*N + gc]; \
        } else { pb0 = make_float4(0,0,0,0); pb1 = pb0; } } }

#define STORET(bb) { \
    split2(pa0.x, pa0.y, Ah[bb][ac0/2  ][ar0   ], Al[bb][ac0/2  ][ar0   ]); \
    split2(pa0.z, pa0.w, Ah[bb][ac0/2+1][ar0   ], Al[bb][ac0/2+1][ar0   ]); \
    split2(pa1.x, pa1.y, Ah[bb][ac0/2  ][ar0+64], Al[bb][ac0/2  ][ar0+64]); \
    split2(pa1.z, pa1.w, Ah[bb][ac0/2+1][ar0+64], Al[bb][ac0/2+1][ar0+64]); \
    if (bact){ \
        split2(pb0.x, pb1.x, Bh[bb][br2][bcc+0], Bl[bb][br2][bcc+0]); \
        split2(pb0.y, pb1.y, Bh[bb][br2][bcc+1], Bl[bb][br2][bcc+1]); \
        split2(pb0.z, pb1.z, Bh[bb][br2][bcc+2], Bl[bb][br2][bcc+2]); \
        split2(pb0.w, pb1.w, Bh[bb][br2][bcc+3], Bl[bb][br2][bcc+3]); } }

    LOADT(0);
    STORET(0);
    __syncthreads();

    int cur = 0;
    for (int k0=0; k0<K; k0+=16){
        const bool more = (k0+16 < K);
        if (more){ LOADT(k0+16); }

        unsigned int ah[4][4], alr[4][4];
#pragma unroll
        for (int t=0;t<4;t++){
            int r = warpM*64 + t*16 + (lane>>2);
            ah[t][0]=Ah[cur][kq  ][r];   alr[t][0]=Al[cur][kq  ][r];
            ah[t][1]=Ah[cur][kq  ][r+8]; alr[t][1]=Al[cur][kq  ][r+8];
            ah[t][2]=Ah[cur][kq+4][r];   alr[t][2]=Al[cur][kq+4][r];
            ah[t][3]=Ah[cur][kq+4][r+8]; alr[t][3]=Al[cur][kq+4][r+8];
        }
        unsigned int bh[JW][2], blr[JW][2];
#pragma unroll
        for (int j=0;j<JW;j++){
            int cb = warpN*WN + j*8 + (lane>>2);
            bh[j][0]=Bh[cur][kq  ][cb];  blr[j][0]=Bl[cur][kq  ][cb];
            bh[j][1]=Bh[cur][kq+4][cb];  blr[j][1]=Bl[cur][kq+4][cb];
        }
#pragma unroll
        for (int t=0;t<4;t++)
#pragma unroll
            for (int j=0;j<JW;j++){
                mma_bf16(acc[t][j], ah[t],  bh[j]);
                mma_bf16(acc[t][j], ah[t],  blr[j]);
                mma_bf16(acc[t][j], alr[t], bh[j]);
            }
        if (more){ STORET(cur^1); }
        __syncthreads();
        cur ^= 1;
    }

    // epilogue
#pragma unroll
    for (int t=0;t<4;t++){
#pragma unroll
        for (int j=0;j<JW;j++){
            int row = rowBase + warpM*64 + t*16 + (lane>>2);
            int col = colBase + warpN*WN + j*8 + 2*(lane&3);
            float b0 = (bias && col   < N) ? bias[col]   : 0.f;
            float b1 = (bias && col+1 < N) ? bias[col+1] : 0.f;
            if (MODE == 0){
                if (col < N){
                    C[(size_t)row*N + col] = acc[t][j][0] + b0;
                    if (col+1 < N) C[(size_t)row*N + col+1] = acc[t][j][1] + b1;
                    C[(size_t)(row+8)*N + col] = acc[t][j][2] + b0;
                    if (col+1 < N) C[(size_t)(row+8)*N + col+1] = acc[t][j][3] + b1;
                }
            } else {
                if (col < N){
                    write_proj(row,   col,   acc[t][j][0] + b0);
                    write_proj(row+8, col,   acc[t][j][2] + b0);
                    if (col+1 < N){
                        write_proj(row,   col+1, acc[t][j][1] + b1);
                        write_proj(row+8, col+1, acc[t][j][3] + b1);
                    }
                }
            }
        }
    }
#undef LOADT
#undef STORET
}

// ---------------- postprocess (tail only): RMSNorm B/C, dt/lam/decay ----------------
__global__ void k_post(const float* __restrict__ wB, const float* __restrict__ wC,
                       const float* __restrict__ biasB, const float* __restrict__ biasC,
                       const float* __restrict__ A_log)
{
    const int l = blockIdx.x;
    const int tid = threadIdx.x;         // 256 threads
    const float* row = g_tail + (size_t)l*TAILW;

    __shared__ float pB[8], pC[8];
    float vB = row[tid];
    float vC = row[256+tid];
    float sB = vB*vB, sC = vC*vC;
#pragma unroll
    for (int o=16;o>0;o>>=1){
        sB += __shfl_xor_sync(0xffffffffu, sB, o);
        sC += __shfl_xor_sync(0xffffffffu, sC, o);
    }
    int wp = tid >> 5;
    if ((tid & 31) == 0){ pB[wp]=sB; pC[wp]=sC; }
    __syncthreads();

    int g = tid >> 6, j = tid & 63;
    float mB = (pB[2*g]+pB[2*g+1]) * (1.f/64.f);
    float mC = (pC[2*g]+pC[2*g+1]) * (1.f/64.f);
    g_Bm[l*256+tid] = vB * rsqrtf(mB + EPSV) * wB[j] + biasB[tid];
    g_Cm[l*256+tid] = vC * rsqrtf(mC + EPSV) * wC[j] + biasC[tid];

    if (tid < GN){
        float dtr = row[512+tid];
        float dt  = (dtr > 20.f) ? dtr : log1pf(expf(dtr));
        float lam = 1.f/(1.f+expf(-row[516+tid]));
        float A   = -expf(A_log[tid]);
        g_scal[l*GN+tid] = make_float4(dt, lam, expf(dt*A), 0.f);
    }
}

// ---------------- dt cumsum (4 sequences of 2048) + per-chunk decays ----------------
__global__ void k_scan_dt(const float* __restrict__ A_log)
{
    int g = threadIdx.x >> 5;
    int lane = threadIdx.x & 31;
    float carry = 0.f;
    for (int b=0;b<64;b++){
        int l = b*32 + lane;
        float v = g_scal[l*GN+g].x;
#pragma unroll
        for (int o=1;o<32;o<<=1){
            float t = __shfl_up_sync(0xffffffffu, v, o);
            if (lane >= o) v += t;
        }
        g_sdt[l*GN+g] = carry + v;
        carry += __shfl_sync(0xffffffffu, v, 31);
    }
    __syncthreads();
    int t = threadIdx.x;
    if (t < NC*GN){
        int c = t >> 2, gg = t & 3;
        float A = -expf(A_log[gg]);
        float e = g_sdt[(c*CH + CH-1)*GN + gg];
        float s = c ? g_sdt[(c*CH - 1)*GN + gg] : 0.f;
        g_Dc[t] = expf(A*(e-s));
    }
}

// ---------------- RoPE applied in-place to Bm, Cm ----------------
__global__ void k_rope(const float* __restrict__ theta_log)
{
    int idx = blockIdx.x*256 + threadIdx.x;
    if (idx >= LSEQ*GN*16) return;
    int j = idx & 15;
    int g = (idx >> 4) & 3;
    int l = idx >> 6;
    float th = expf(theta_log[g*16+j]);
    float ang = g_sdt[l*GN+g] * th;
    float cs = cosf(ang), sn = sinf(ang);
    int base = l*256 + g*64 + j*4;
#pragma unroll
    for (int r=0;r<2;r++){
        float re = g_Bm[base+r],   im = g_Bm[base+2+r];
        g_Bm[base+r]   = re*cs - im*sn;
        g_Bm[base+2+r] = re*sn + im*cs;
        float re2 = g_Cm[base+r],  im2 = g_Cm[base+2+r];
        g_Cm[base+r]   = re2*cs - im2*sn;
        g_Cm[base+2+r] = re2*sn + im2*cs;
    }
}

// ---------------- x_up = xsilu[L*H,64] @ W_xup[64,128], 64 rows/block ----------------
__global__ __launch_bounds__(256) void k_xup(const float* __restrict__ Wx)
{
    __shared__ float Ws[64][128];
    __shared__ float Xs[64][64];
    int tid = threadIdx.x;  // 256
    for (int i=tid;i<64*128;i+=256) Ws[i>>7][i&127] = Wx[i];
    int m0 = blockIdx.x*64;
    for (int i=tid;i<64*64;i+=256)  Xs[i>>6][i&63]  = g_xsilu[(size_t)(m0 + (i>>6))*64 + (i&63)];
    __syncthreads();
    int col = (tid & 31)*4;
    int rb  = (tid >> 5)*8;            // 8 rows per thread
    float a[8][4];
#pragma unroll
    for (int i=0;i<8;i++)
#pragma unroll
        for (int q=0;q<4;q++) a[i][q]=0.f;
#pragma unroll 2
    for (int k=0;k<64;k++){
        float4 w = *(const float4*)&Ws[k][col];
#pragma unroll
        for (int i=0;i<8;i++){
            float x = Xs[rb+i][k];
            a[i][0]+=x*w.x; a[i][1]+=x*w.y; a[i][2]+=x*w.z; a[i][3]+=x*w.w;
        }
    }
#pragma unroll
    for (int i=0;i<8;i++)
        *(float4*)&g_xup[(size_t)(m0+rb+i)*128 + col] = make_float4(a[i][0],a[i][1],a[i][2],a[i][3]);
}

// ---------------- scanY: chunk-local scan from zero state; emits y_local AND final state F ----------------
__global__ void k_scanY()
{
    const int c = blockIdx.z, h = blockIdx.y;
    const int p = blockIdx.x*4 + (threadIdx.x >> 5);
    const int n = threadIdx.x & 31;
    const int g = h >> 2;
    const int t0 = c*CH;

    float u_prev = 0.f;
    if (c){
        int t = t0-1;
        float2 B = *(const float2*)&g_Bm[(t*GN+g)*64 + n*2];
        float2 X = *(const float2*)&g_xup[(size_t)(t*HH+h)*128 + p*2];
        float4 s = g_scal[t*GN+g];
        u_prev = s.x*(B.x*X.x + B.y*X.y);
    }
    float hs = 0.f;
    const bool isLane0  = (n == 0);
    const bool isLane16 = (n == 16);
    const bool low = (n < 16);
#pragma unroll 2
    for (int t=t0; t<t0+CH; t++){
        float2 B = *(const float2*)&g_Bm[(t*GN+g)*64 + n*2];
        float2 X = *(const float2*)&g_xup[(size_t)(t*HH+h)*128 + p*2];
        float4 s = g_scal[t*GN+g];
        float uss = s.x*(B.x*X.x + B.y*X.y);
        float ut  = s.y*uss + (1.f-s.y)*u_prev;
        u_prev = uss;
        hs = hs*s.z + ut;

        float2 Cv = *(const float2*)&g_Cm[(t*GN+g)*64 + n*2];
        float y0 = hs*Cv.x, y1 = hs*Cv.y;
        float t0s = __shfl_xor_sync(0xffffffffu, y0, 16);
        float t1s = __shfl_xor_sync(0xffffffffu, y1, 16);
        float v = low ? (y0 + t0s) : (y1 + t1s);
#pragma unroll
        for (int o=8;o>0;o>>=1) v += __shfl_xor_sync(0xffffffffu, v, o);
        float* dst = &g_yraw[(size_t)(t*HH+h)*128 + p*2];
        if (isLane0)  dst[0] = v;
        if (isLane16) dst[1] = v;
    }
    g_F[((c*HH+h)*PP+p)*NS + n] = hs;
}

// ---------------- pass B: inter-chunk combine (16-step scan) ----------------
__global__ void k_passB()
{
    int gw = blockIdx.x*8 + (threadIdx.x >> 5);   // 1024 warps total
    int n  = threadIdx.x & 31;
    int h = gw >> 6, p = gw & 63;
    int g = h >> 2;
    float S = 0.f;
#pragma unroll
    for (int c=0;c<NC;c++){
        int idx = ((c*HH+h)*PP+p)*NS + n;
        g_S[idx] = S;
        S = S*g_Dc[c*GN+g] + g_F[idx];
    }
}

// ---------------- passCorr: y[t] += dd[t] * sum_n C[t,n,r]*S[p,n]  (chunks 1..15) ----------------
__global__ __launch_bounds__(256) void k_passCorr(const float* __restrict__ A_log)
{
    const int c = blockIdx.x + 1;     // 1..15
    const int h = blockIdx.y;
    const int g = h >> 2;
    const int tid  = threadIdx.x;
    const int lane = tid & 31;
    const int warp = tid >> 5;
    const int t0 = c*CH;

    __shared__ float Cs[128][66];
    __shared__ float Ss[64][33];
    __shared__ float dd[128];

    // stage C chunk (128 t x 64) as float2 loads
    for (int i = tid; i < 128*32; i += 256){
        int t = i >> 5, nn = (i & 31)*2;
        float2 v = *(const float2*)&g_Cm[((t0+t)*GN+g)*64 + nn];
        Cs[t][nn] = v.x; Cs[t][nn+1] = v.y;
    }
    // stage S (64 p x 32 n)
    for (int i = tid; i < 64*32; i += 256){
        int p = i >> 5, nn = i & 31;
        Ss[p][nn] = g_S[((c*HH+h)*PP+p)*NS + nn];
    }
    if (tid < 128){
        float A = -expf(A_log[g]);
        float base = g_sdt[(t0-1)*GN+g];
        dd[tid] = expf(A*(g_sdt[(t0+tid)*GN+g] - base));
    }
    __syncthreads();

    // each warp handles 16 consecutive t
#pragma unroll 1
    for (int i = 0; i < 16; i++){
        int t = warp*16 + i;
        float y00=0.f, y01=0.f, y10=0.f, y11=0.f;
#pragma unroll 8
        for (int n=0;n<32;n++){
            float c0 = Cs[t][2*n], c1 = Cs[t][2*n+1];
            float s0 = Ss[lane][n], s1 = Ss[lane+32][n];
            y00 += c0*s0; y01 += c1*s0;
            y10 += c0*s1; y11 += c1*s1;
        }
        float d = dd[t];
        float* dst = &g_yraw[(size_t)((t0+t)*HH+h)*128];
        float2 a = *(float2*)&dst[lane*2];
        a.x += d*y00; a.y += d*y01;
        *(float2*)&dst[lane*2] = a;
        float2 b2 = *(float2*)&dst[(lane+32)*2];
        b2.x += d*y10; b2.y += d*y11;
        *(float2*)&dst[(lane+32)*2] = b2;
    }
}

// ---------------- ydown + skip + z-gate ----------------
__global__ void k_ydown(const float* __restrict__ Wy, const float* __restrict__ Dp)
{
    __shared__ float Ws[128][64];
    __shared__ float Ys[16][128];
    int tid = threadIdx.x;  // 128
    for (int i=tid;i<128*64;i+=128) Ws[i>>6][i&63]  = Wy[i];
    int m0 = blockIdx.x*16;
    for (int i=tid;i<16*128;i+=128) Ys[i>>7][i&127] = g_yraw[(size_t)(m0 + (i>>7))*128 + (i&127)];
    __syncthreads();
    int col = (tid & 15)*4;
    int r0  = (tid >> 4)*2;
    float a0c[4]={0,0,0,0}, a1c[4]={0,0,0,0};
#pragma unroll 4
    for (int k=0;k<128;k++){
        float a0 = Ys[r0][k], a1 = Ys[r0+1][k];
        float4 w = *(const float4*)&Ws[k][col];
        a0c[0]+=a0*w.x; a0c[1]+=a0*w.y; a0c[2]+=a0*w.z; a0c[3]+=a0*w.w;
        a1c[0]+=a1*w.x; a1c[1]+=a1*w.y; a1c[2]+=a1*w.z; a1c[3]+=a1*w.w;
    }
#pragma unroll
    for (int rr=0;rr<2;rr++){
        int m = m0 + r0 + rr;
        int hh = m & 15;
        float dv = Dp[hh];
        float* accp = rr ? a1c : a0c;
#pragma unroll
        for (int j2=0;j2<4;j2++){
            int o = m*64 + col + j2;
            float v = accp[j2] + dv * g_xsilu[o];
            g_y3[o] = v * g_zsilu[o];
        }
    }
}

// ---------------- launch ----------------
extern "C" void kernel_launch(void* const* d_in, const int* in_sizes, int n_in,
                              void* d_out, int out_size)
{
    const float* u        = (const float*)d_in[0];
    const float* W_in     = (const float*)d_in[1];
    const float* b_in     = (const float*)d_in[2];
    const float* W_xup    = (const float*)d_in[3];
    const float* W_ydown  = (const float*)d_in[4];
    const float* A_log    = (const float*)d_in[5];
    const float* theta_log= (const float*)d_in[6];
    const float* D_param  = (const float*)d_in[7];
    const float* wB       = (const float*)d_in[8];
    const float* wC       = (const float*)d_in[9];
    const float* bias_B   = (const float*)d_in[10];
    const float* bias_C   = (const float*)d_in[11];
    const float* W_out    = (const float*)d_in[12];
    float* out = (float*)d_out;

    float *p_y3;
    cudaGetSymbolAddress((void**)&p_y3, g_y3);

    // 1. proj = u @ W_in + b_in  [2048 x 2568, K=512], fused silu/tail epilogue
    {
        dim3 grid((DPROJ + 127)/128, LSEQ/128);
        k_gemm_bf16s<128,1><<<grid, 256>>>(LSEQ, DPROJ, DMODEL, u, W_in, b_in, nullptr);
    }
    // 2. rmsnorm B/C + dt/lam (tail only)
    k_post<<<LSEQ, 256>>>(wB, wC, bias_B, bias_C, A_log);
    // 3. dt cumsum + chunk decays
    k_scan_dt<<<1, 128>>>(A_log);
    // 4. RoPE
    k_rope<<<(LSEQ*GN*16 + 255)/256, 256>>>(theta_log);
    // 5. x_up
    k_xup<<<(LSEQ*HH)/64, 256>>>(W_xup);
    // 6. chunk-local scan: y_local + final states (passA eliminated)
    k_scanY<<<dim3(16, HH, NC), 128>>>();
    // 7. inter-chunk combine
    k_passB<<<128, 256>>>();
    // 8. state correction: y += dd * C.S
    k_passCorr<<<dim3(NC-1, HH), 256>>>(A_log);
    // 9. ydown + skip + gate
    k_ydown<<<(LSEQ*HH)/16, 128>>>(W_ydown, D_param);
    // 10. out = y3 @ W_out  [2048 x 512, K=1024]
    {
        dim3 grid(DMODEL/64, LSEQ/128);
        k_gemm_bf16s<64,0><<<grid, 256>>>(LSEQ, DMODEL, 1024, p_y3, W_out, nullptr, out);
    }
}